// round 15
// baseline (speedup 1.0000x reference)
#include <cuda_runtime.h>
#include <cuda_fp16.h>

#define NN   200000
#define DIM  64
#define NV   (NN * DIM)
#define EMAX 1250000
#define ALPHA 0.25f
#define NB_SCAN ((NN + 1023) / 1024)   // 196

// Scratch (device globals — no allocation allowed).
// NOTE: never pass these symbols from host code; select inside kernels.
// fp16 node rows: [NN][64] halves = [NN][16] uint2 (4 halves per lane).
// g_deg/g_cur are zeroed at the END of each launch (by k_score); BSS zero
// covers the very first call. Every call does identical work.
__device__ uint2 g_h0[NN * 16];    // fp16(emb)
__device__ uint2 g_x1h[NN * 16];
__device__ uint2 g_x2h[NN * 16];
__device__ uint2 g_outh[NN * 16];  // fp16 final embedding
__device__ float g_dis[NN];
__device__ int   g_deg[NN];
__device__ int   g_off[NN];        // block-local exclusive prefix
__device__ int   g_cur[NN];
__device__ int   g_bsum[NB_SCAN];
__device__ int   g_bpre[NB_SCAN];
__device__ int   g_src[EMAX];
__device__ float g_wgt[EMAX];

__device__ __forceinline__ float4 h4_to_f4(uint2 u) {
    __half2 h01 = *reinterpret_cast<__half2*>(&u.x);
    __half2 h23 = *reinterpret_cast<__half2*>(&u.y);
    float2 f01 = __half22float2(h01);
    float2 f23 = __half22float2(h23);
    return make_float4(f01.x, f01.y, f23.x, f23.y);
}

__device__ __forceinline__ uint2 f4_to_h4(float4 f) {
    __half2 h01 = __float22half2_rn(make_float2(f.x, f.y));
    __half2 h23 = __float22half2_rn(make_float2(f.z, f.w));
    uint2 u;
    u.x = *reinterpret_cast<unsigned int*>(&h01);
    u.y = *reinterpret_cast<unsigned int*>(&h23);
    return u;
}

// ---- degree count (4 edges/thread, pipelined atomics) fused with
// emb -> fp16 conversion. Requires g_deg == 0 on entry. ----
__global__ void k_count_half(const int* __restrict__ col,
                             const float* __restrict__ emb, int E) {
    int i = blockIdx.x * blockDim.x + threadIdx.x;
    int e4 = E >> 2;   // E divisible by 4 (1,250,000)
    if (i < e4) {
        int4 c4 = __ldg((const int4*)col + i);
        atomicAdd(&g_deg[c4.x], 1);
        atomicAdd(&g_deg[c4.y], 1);
        atomicAdd(&g_deg[c4.z], 1);
        atomicAdd(&g_deg[c4.w], 1);
    } else if ((i << 2) < E) {   // tail if E % 4 != 0
        for (int e = i << 2; e < E; e++) atomicAdd(&g_deg[__ldg(col + e)], 1);
    }
    if (i < NV / 4) {
        float4 v = __ldg((const float4*)emb + i);
        g_h0[i] = f4_to_h4(v);
    }
}

// ---- block scan of degrees (warp-shuffle), fused with dis = deg^{-1/2} ----
__global__ void k_scan1() {
    __shared__ int wsum[32];
    int tid = threadIdx.x;
    int lane = tid & 31, wid = tid >> 5;
    int i = blockIdx.x * 1024 + tid;
    int v = (i < NN) ? g_deg[i] : 0;
    if (i < NN) g_dis[i] = (v > 0) ? rsqrtf((float)v) : 0.f;

    int x = v;
    #pragma unroll
    for (int o = 1; o < 32; o <<= 1) {
        int y = __shfl_up_sync(0xFFFFFFFFu, x, o);
        if (lane >= o) x += y;
    }
    if (lane == 31) wsum[wid] = x;
    __syncthreads();
    if (wid == 0) {
        int s = wsum[lane];
        #pragma unroll
        for (int o = 1; o < 32; o <<= 1) {
            int y = __shfl_up_sync(0xFFFFFFFFu, s, o);
            if (lane >= o) s += y;
        }
        wsum[lane] = s;
    }
    __syncthreads();
    int incl = x + ((wid > 0) ? wsum[wid - 1] : 0);
    if (i < NN) g_off[i] = incl - v;   // block-local exclusive
    if (tid == 1023) g_bsum[blockIdx.x] = incl;
}

// ---- scan of block sums (196 elements) ----
__global__ void k_scan2() {
    __shared__ int s[256];
    int tid = threadIdx.x;
    int v = (tid < NB_SCAN) ? g_bsum[tid] : 0;
    s[tid] = v;
    __syncthreads();
    #pragma unroll
    for (int o = 1; o < 256; o <<= 1) {
        int t = (tid >= o) ? s[tid - o] : 0;
        __syncthreads();
        s[tid] += t;
        __syncthreads();
    }
    if (tid < NB_SCAN) g_bpre[tid] = s[tid] - v;
}

// ---- CSR fill: 4 edges per thread -> 4 independent (pipelined) atomics.
// Requires g_cur == 0 on entry. ----
__global__ void k_fill(const int* __restrict__ row, const int* __restrict__ col, int E) {
    int i = blockIdx.x * blockDim.x + threadIdx.x;
    int e4 = E >> 2;
    if (i < e4) {
        int4 r4 = __ldg((const int4*)row + i);
        int4 c4 = __ldg((const int4*)col + i);
        int s0 = __ldg(g_off + c4.x) + __ldg(g_bpre + (c4.x >> 10)) + atomicAdd(&g_cur[c4.x], 1);
        int s1 = __ldg(g_off + c4.y) + __ldg(g_bpre + (c4.y >> 10)) + atomicAdd(&g_cur[c4.y], 1);
        int s2 = __ldg(g_off + c4.z) + __ldg(g_bpre + (c4.z >> 10)) + atomicAdd(&g_cur[c4.z], 1);
        int s3 = __ldg(g_off + c4.w) + __ldg(g_bpre + (c4.w >> 10)) + atomicAdd(&g_cur[c4.w], 1);
        float dc0 = __ldg(g_dis + c4.x), dc1 = __ldg(g_dis + c4.y);
        float dc2 = __ldg(g_dis + c4.z), dc3 = __ldg(g_dis + c4.w);
        float dr0 = __ldg(g_dis + r4.x), dr1 = __ldg(g_dis + r4.y);
        float dr2 = __ldg(g_dis + r4.z), dr3 = __ldg(g_dis + r4.w);
        g_src[s0] = r4.x; g_wgt[s0] = dr0 * dc0;
        g_src[s1] = r4.y; g_wgt[s1] = dr1 * dc1;
        g_src[s2] = r4.z; g_wgt[s2] = dr2 * dc2;
        g_src[s3] = r4.w; g_wgt[s3] = dr3 * dc3;
    } else if ((i << 2) < E) {   // tail if E % 4 != 0
        for (int e = i << 2; e < E; e++) {
            int r = __ldg(row + e);
            int c = __ldg(col + e);
            int slot = __ldg(g_off + c) + __ldg(g_bpre + (c >> 10)) + atomicAdd(&g_cur[c], 1);
            g_src[slot] = r;
            g_wgt[slot] = __ldg(g_dis + r) * __ldg(g_dis + c);
        }
    }
}

// ---- fp16 gather SpMM (R4 structure): 16 lanes per node, unroll-4,
// 4 independent fp32 accumulators, 8B row loads.
// layer 0: g_h0 -> g_x1h ; layer 1: g_x1h -> g_x2h
__global__ void k_gather(int layer) {
    int t = blockIdx.x * blockDim.x + threadIdx.x;
    int node = t >> 4;
    int j = t & 15;
    if (node >= NN) return;

    const uint2* x  = (layer == 0) ? g_h0  : g_x1h;
    uint2*       xn = (layer == 0) ? g_x1h : g_x2h;

    int beg = __ldg(g_off + node) + __ldg(g_bpre + (node >> 10));
    int end = beg + __ldg(g_deg + node);
    float4 A0 = make_float4(0.f, 0.f, 0.f, 0.f), A1 = A0, A2 = A0, A3 = A0;

    int k = beg;
    for (; k + 4 <= end; k += 4) {
        int r0 = __ldg(g_src + k);
        int r1 = __ldg(g_src + k + 1);
        int r2 = __ldg(g_src + k + 2);
        int r3 = __ldg(g_src + k + 3);
        float w0 = __ldg(g_wgt + k);
        float w1 = __ldg(g_wgt + k + 1);
        float w2 = __ldg(g_wgt + k + 2);
        float w3 = __ldg(g_wgt + k + 3);
        float4 v0 = h4_to_f4(__ldg(x + (size_t)r0 * 16 + j));
        float4 v1 = h4_to_f4(__ldg(x + (size_t)r1 * 16 + j));
        float4 v2 = h4_to_f4(__ldg(x + (size_t)r2 * 16 + j));
        float4 v3 = h4_to_f4(__ldg(x + (size_t)r3 * 16 + j));
        A0.x += w0 * v0.x; A0.y += w0 * v0.y; A0.z += w0 * v0.z; A0.w += w0 * v0.w;
        A1.x += w1 * v1.x; A1.y += w1 * v1.y; A1.z += w1 * v1.z; A1.w += w1 * v1.w;
        A2.x += w2 * v2.x; A2.y += w2 * v2.y; A2.z += w2 * v2.z; A2.w += w2 * v2.w;
        A3.x += w3 * v3.x; A3.y += w3 * v3.y; A3.z += w3 * v3.z; A3.w += w3 * v3.w;
    }
    if (k + 2 <= end) {
        int r0 = __ldg(g_src + k);
        int r1 = __ldg(g_src + k + 1);
        float w0 = __ldg(g_wgt + k);
        float w1 = __ldg(g_wgt + k + 1);
        float4 v0 = h4_to_f4(__ldg(x + (size_t)r0 * 16 + j));
        float4 v1 = h4_to_f4(__ldg(x + (size_t)r1 * 16 + j));
        A0.x += w0 * v0.x; A0.y += w0 * v0.y; A0.z += w0 * v0.z; A0.w += w0 * v0.w;
        A1.x += w1 * v1.x; A1.y += w1 * v1.y; A1.z += w1 * v1.z; A1.w += w1 * v1.w;
        k += 2;
    }
    if (k < end) {
        int r0 = __ldg(g_src + k);
        float w0 = __ldg(g_wgt + k);
        float4 v0 = h4_to_f4(__ldg(x + (size_t)r0 * 16 + j));
        A2.x += w0 * v0.x; A2.y += w0 * v0.y; A2.z += w0 * v0.z; A2.w += w0 * v0.w;
    }

    float4 acc;
    acc.x = (A0.x + A1.x) + (A2.x + A3.x);
    acc.y = (A0.y + A1.y) + (A2.y + A3.y);
    acc.z = (A0.z + A1.z) + (A2.z + A3.z);
    acc.w = (A0.w + A1.w) + (A2.w + A3.w);
    xn[(size_t)node * 16 + j] = f4_to_h4(acc);
}

// ---- final layer fused with alpha-combine, all-fp16 operands:
// outh = fp16( 0.25*(h0 + x1 + x2 + gather(x2)) ) ----
__global__ void k_gather_final() {
    int t = blockIdx.x * blockDim.x + threadIdx.x;
    int node = t >> 4;
    int j = t & 15;
    if (node >= NN) return;

    const uint2* x = g_x2h;
    int beg = __ldg(g_off + node) + __ldg(g_bpre + (node >> 10));
    int end = beg + __ldg(g_deg + node);
    float4 A0 = make_float4(0.f, 0.f, 0.f, 0.f), A1 = A0, A2 = A0, A3 = A0;

    int k = beg;
    for (; k + 4 <= end; k += 4) {
        int r0 = __ldg(g_src + k);
        int r1 = __ldg(g_src + k + 1);
        int r2 = __ldg(g_src + k + 2);
        int r3 = __ldg(g_src + k + 3);
        float w0 = __ldg(g_wgt + k);
        float w1 = __ldg(g_wgt + k + 1);
        float w2 = __ldg(g_wgt + k + 2);
        float w3 = __ldg(g_wgt + k + 3);
        float4 v0 = h4_to_f4(__ldg(x + (size_t)r0 * 16 + j));
        float4 v1 = h4_to_f4(__ldg(x + (size_t)r1 * 16 + j));
        float4 v2 = h4_to_f4(__ldg(x + (size_t)r2 * 16 + j));
        float4 v3 = h4_to_f4(__ldg(x + (size_t)r3 * 16 + j));
        A0.x += w0 * v0.x; A0.y += w0 * v0.y; A0.z += w0 * v0.z; A0.w += w0 * v0.w;
        A1.x += w1 * v1.x; A1.y += w1 * v1.y; A1.z += w1 * v1.z; A1.w += w1 * v1.w;
        A2.x += w2 * v2.x; A2.y += w2 * v2.y; A2.z += w2 * v2.z; A2.w += w2 * v2.w;
        A3.x += w3 * v3.x; A3.y += w3 * v3.y; A3.z += w3 * v3.z; A3.w += w3 * v3.w;
    }
    if (k + 2 <= end) {
        int r0 = __ldg(g_src + k);
        int r1 = __ldg(g_src + k + 1);
        float w0 = __ldg(g_wgt + k);
        float w1 = __ldg(g_wgt + k + 1);
        float4 v0 = h4_to_f4(__ldg(x + (size_t)r0 * 16 + j));
        float4 v1 = h4_to_f4(__ldg(x + (size_t)r1 * 16 + j));
        A0.x += w0 * v0.x; A0.y += w0 * v0.y; A0.z += w0 * v0.z; A0.w += w0 * v0.w;
        A1.x += w1 * v1.x; A1.y += w1 * v1.y; A1.z += w1 * v1.z; A1.w += w1 * v1.w;
        k += 2;
    }
    if (k < end) {
        int r0 = __ldg(g_src + k);
        float w0 = __ldg(g_wgt + k);
        float4 v0 = h4_to_f4(__ldg(x + (size_t)r0 * 16 + j));
        A2.x += w0 * v0.x; A2.y += w0 * v0.y; A2.z += w0 * v0.z; A2.w += w0 * v0.w;
    }

    size_t idx = (size_t)node * 16 + j;
    float4 a = h4_to_f4(g_h0[idx]);
    float4 b = h4_to_f4(g_x1h[idx]);
    float4 c = h4_to_f4(g_x2h[idx]);
    float4 o;
    o.x = ALPHA * (a.x + b.x + c.x + ((A0.x + A1.x) + (A2.x + A3.x)));
    o.y = ALPHA * (a.y + b.y + c.y + ((A0.y + A1.y) + (A2.y + A3.y)));
    o.z = ALPHA * (a.z + b.z + c.z + ((A0.z + A1.z) + (A2.z + A3.z)));
    o.w = ALPHA * (a.w + b.w + c.w + ((A0.w + A1.w) + (A2.w + A3.w)));
    g_outh[idx] = f4_to_h4(o);
}

// ---- scoring: 8 lanes per pair, 16B fp16 loads, fp32 acc.
// Also re-zeroes g_deg/g_cur for the next invocation. ----
__global__ void k_score(const int* __restrict__ batch, float* __restrict__ out, int P) {
    int t = blockIdx.x * blockDim.x + threadIdx.x;
    if (t < NN) { g_deg[t] = 0; g_cur[t] = 0; }
    int p = t >> 3;
    int lane = t & 7;
    if (p >= P) return;
    int u = __ldg(batch + 3 * p);
    int v = __ldg(batch + 3 * p + 1);
    uint4 ua = __ldg((const uint4*)g_outh + (size_t)u * 8 + lane);
    uint4 ub = __ldg((const uint4*)g_outh + (size_t)v * 8 + lane);
    float4 a0 = h4_to_f4(make_uint2(ua.x, ua.y));
    float4 a1 = h4_to_f4(make_uint2(ua.z, ua.w));
    float4 b0 = h4_to_f4(make_uint2(ub.x, ub.y));
    float4 b1 = h4_to_f4(make_uint2(ub.z, ub.w));
    float s = a0.x * b0.x + a0.y * b0.y + a0.z * b0.z + a0.w * b0.w
            + a1.x * b1.x + a1.y * b1.y + a1.z * b1.z + a1.w * b1.w;
    #pragma unroll
    for (int o = 4; o; o >>= 1) s += __shfl_xor_sync(0xFFFFFFFFu, s, o);
    if (lane == 0) out[p] = s;
}

extern "C" void kernel_launch(void* const* d_in, const int* in_sizes, int n_in,
                              void* d_out, int out_size) {
    const float* emb   = (const float*)d_in[0];
    const int*   ei    = (const int*)d_in[1];
    const int*   batch = (const int*)d_in[2];
    float*       out   = (float*)d_out;

    int E = in_sizes[1] / 2;
    const int* row = ei;
    const int* col = ei + E;
    int P = in_sizes[2] / 3;

    k_count_half<<<(NV / 4 + 255) / 256, 256>>>(col, emb, E);
    k_scan1<<<NB_SCAN, 1024>>>();
    k_scan2<<<1, 256>>>();
    int fthreads = (E + 3) / 4;
    k_fill<<<(fthreads + 255) / 256, 256>>>(row, col, E);

    int gthreads = NN * 16;
    int gblocks = (gthreads + 255) / 256;
    k_gather<<<gblocks, 256>>>(0);
    k_gather<<<gblocks, 256>>>(1);
    k_gather_final<<<gblocks, 256>>>();

    long long sthreads = (long long)P * 8;
    k_score<<<(int)((sthreads + 255) / 256), 256>>>(batch, out, P);
}

// round 16
// speedup vs baseline: 1.1229x; 1.1229x over previous
#include <cuda_runtime.h>
#include <cuda_fp16.h>

#define NN   200000
#define DIM  64
#define NV   (NN * DIM)
#define EMAX 1250000
#define ALPHA 0.25f
#define NB_SCAN ((NN + 1023) / 1024)   // 196

// Scratch (device globals — no allocation allowed).
// NOTE: never pass these symbols from host code; select inside kernels.
// fp16 node rows: [NN][64] halves = [NN][16] uint2.
// z-representation: z_l = D^{-1/2} x_l  =>  z_{l+1} = D^{-1} A z_l (weight-free).
// g_deg/g_cur zeroed at END of each launch (k_score); BSS zero covers call 1.
__device__ uint2  g_h0[NN * 16];    // fp16(emb) = x0
__device__ uint2  g_z1h[NN * 16];   // fp16 z1
__device__ uint2  g_z2h[NN * 16];   // fp16 z2
__device__ uint2  g_outh[NN * 16];  // fp16 final embedding
__device__ float  g_dis[NN];        // deg^{-1/2} (0 if deg==0)
__device__ float2 g_si[NN];         // {inv = 1/deg (0 if deg==0), s = sqrt(deg)}
__device__ int    g_deg[NN];
__device__ int    g_off[NN];        // block-local exclusive prefix
__device__ int    g_cur[NN];
__device__ int    g_bsum[NB_SCAN];
__device__ int    g_bpre[NB_SCAN];
__device__ int    g_src[EMAX];

__device__ __forceinline__ float4 h4_to_f4(uint2 u) {
    __half2 h01 = *reinterpret_cast<__half2*>(&u.x);
    __half2 h23 = *reinterpret_cast<__half2*>(&u.y);
    float2 f01 = __half22float2(h01);
    float2 f23 = __half22float2(h23);
    return make_float4(f01.x, f01.y, f23.x, f23.y);
}

__device__ __forceinline__ uint2 f4_to_h4(float4 f) {
    __half2 h01 = __float22half2_rn(make_float2(f.x, f.y));
    __half2 h23 = __float22half2_rn(make_float2(f.z, f.w));
    uint2 u;
    u.x = *reinterpret_cast<unsigned int*>(&h01);
    u.y = *reinterpret_cast<unsigned int*>(&h23);
    return u;
}

// ---- degree count fused with emb -> fp16 conversion ----
// Requires g_deg == 0 on entry.
__global__ void k_count_half(const int* __restrict__ col,
                             const float* __restrict__ emb, int E) {
    int i = blockIdx.x * blockDim.x + threadIdx.x;
    if (i < E) atomicAdd(&g_deg[col[i]], 1);
    if (i < NV / 4) {
        float4 v = __ldg((const float4*)emb + i);
        g_h0[i] = f4_to_h4(v);
    }
}

// ---- block scan of degrees (warp-shuffle), fused with dis / inv / s ----
__global__ void k_scan1() {
    __shared__ int wsum[32];
    int tid = threadIdx.x;
    int lane = tid & 31, wid = tid >> 5;
    int i = blockIdx.x * 1024 + tid;
    int v = (i < NN) ? g_deg[i] : 0;
    if (i < NN) {
        float fd = (float)v;
        g_dis[i] = (v > 0) ? rsqrtf(fd) : 0.f;
        g_si[i] = make_float2((v > 0) ? 1.f / fd : 0.f, sqrtf(fd));
    }

    int x = v;
    #pragma unroll
    for (int o = 1; o < 32; o <<= 1) {
        int y = __shfl_up_sync(0xFFFFFFFFu, x, o);
        if (lane >= o) x += y;
    }
    if (lane == 31) wsum[wid] = x;
    __syncthreads();
    if (wid == 0) {
        int s = wsum[lane];
        #pragma unroll
        for (int o = 1; o < 32; o <<= 1) {
            int y = __shfl_up_sync(0xFFFFFFFFu, s, o);
            if (lane >= o) s += y;
        }
        wsum[lane] = s;
    }
    __syncthreads();
    int incl = x + ((wid > 0) ? wsum[wid - 1] : 0);
    if (i < NN) g_off[i] = incl - v;   // block-local exclusive
    if (tid == 1023) g_bsum[blockIdx.x] = incl;
}

// ---- scan of block sums (196 elements) ----
__global__ void k_scan2() {
    __shared__ int s[256];
    int tid = threadIdx.x;
    int v = (tid < NB_SCAN) ? g_bsum[tid] : 0;
    s[tid] = v;
    __syncthreads();
    #pragma unroll
    for (int o = 1; o < 256; o <<= 1) {
        int t = (tid >= o) ? s[tid - o] : 0;
        __syncthreads();
        s[tid] += t;
        __syncthreads();
    }
    if (tid < NB_SCAN) g_bpre[tid] = s[tid] - v;
}

// ---- CSR fill: src index only (weight-free). 1 edge/thread (R14-proven).
// Requires g_cur == 0 on entry. ----
__global__ void k_fill(const int* __restrict__ row, const int* __restrict__ col, int E) {
    int e = blockIdx.x * blockDim.x + threadIdx.x;
    if (e >= E) return;
    int r = __ldg(row + e);
    int c = __ldg(col + e);
    int slot = __ldg(g_off + c) + __ldg(g_bpre + (c >> 10)) + atomicAdd(&g_cur[c], 1);
    g_src[slot] = r;
}

// ---- layer 0: z1[c] = inv[c] * sum_r dis[r] * h0[r]  (dis gathers hit L2) ----
__global__ void k_gather0() {
    int t = blockIdx.x * blockDim.x + threadIdx.x;
    int node = t >> 4;
    int j = t & 15;
    if (node >= NN) return;

    int beg = __ldg(g_off + node) + __ldg(g_bpre + (node >> 10));
    int end = beg + __ldg(g_deg + node);
    float4 A0 = make_float4(0.f, 0.f, 0.f, 0.f), A1 = A0, A2 = A0, A3 = A0;

    int k = beg;
    for (; k + 4 <= end; k += 4) {
        int r0 = __ldg(g_src + k);
        int r1 = __ldg(g_src + k + 1);
        int r2 = __ldg(g_src + k + 2);
        int r3 = __ldg(g_src + k + 3);
        float w0 = __ldg(g_dis + r0);
        float w1 = __ldg(g_dis + r1);
        float w2 = __ldg(g_dis + r2);
        float w3 = __ldg(g_dis + r3);
        float4 v0 = h4_to_f4(__ldg(g_h0 + (size_t)r0 * 16 + j));
        float4 v1 = h4_to_f4(__ldg(g_h0 + (size_t)r1 * 16 + j));
        float4 v2 = h4_to_f4(__ldg(g_h0 + (size_t)r2 * 16 + j));
        float4 v3 = h4_to_f4(__ldg(g_h0 + (size_t)r3 * 16 + j));
        A0.x += w0 * v0.x; A0.y += w0 * v0.y; A0.z += w0 * v0.z; A0.w += w0 * v0.w;
        A1.x += w1 * v1.x; A1.y += w1 * v1.y; A1.z += w1 * v1.z; A1.w += w1 * v1.w;
        A2.x += w2 * v2.x; A2.y += w2 * v2.y; A2.z += w2 * v2.z; A2.w += w2 * v2.w;
        A3.x += w3 * v3.x; A3.y += w3 * v3.y; A3.z += w3 * v3.z; A3.w += w3 * v3.w;
    }
    if (k + 2 <= end) {
        int r0 = __ldg(g_src + k);
        int r1 = __ldg(g_src + k + 1);
        float w0 = __ldg(g_dis + r0);
        float w1 = __ldg(g_dis + r1);
        float4 v0 = h4_to_f4(__ldg(g_h0 + (size_t)r0 * 16 + j));
        float4 v1 = h4_to_f4(__ldg(g_h0 + (size_t)r1 * 16 + j));
        A0.x += w0 * v0.x; A0.y += w0 * v0.y; A0.z += w0 * v0.z; A0.w += w0 * v0.w;
        A1.x += w1 * v1.x; A1.y += w1 * v1.y; A1.z += w1 * v1.z; A1.w += w1 * v1.w;
        k += 2;
    }
    if (k < end) {
        int r0 = __ldg(g_src + k);
        float w0 = __ldg(g_dis + r0);
        float4 v0 = h4_to_f4(__ldg(g_h0 + (size_t)r0 * 16 + j));
        A2.x += w0 * v0.x; A2.y += w0 * v0.y; A2.z += w0 * v0.z; A2.w += w0 * v0.w;
    }

    float inv = __ldg((const float*)&g_si[node].x);
    float4 acc;
    acc.x = inv * ((A0.x + A1.x) + (A2.x + A3.x));
    acc.y = inv * ((A0.y + A1.y) + (A2.y + A3.y));
    acc.z = inv * ((A0.z + A1.z) + (A2.z + A3.z));
    acc.w = inv * ((A0.w + A1.w) + (A2.w + A3.w));
    g_z1h[(size_t)node * 16 + j] = f4_to_h4(acc);
}

// ---- layer 1: z2[c] = inv[c] * sum_r z1[r]  (weight-free inner loop) ----
__global__ void k_gather1() {
    int t = blockIdx.x * blockDim.x + threadIdx.x;
    int node = t >> 4;
    int j = t & 15;
    if (node >= NN) return;

    int beg = __ldg(g_off + node) + __ldg(g_bpre + (node >> 10));
    int end = beg + __ldg(g_deg + node);
    float4 A0 = make_float4(0.f, 0.f, 0.f, 0.f), A1 = A0, A2 = A0, A3 = A0;

    int k = beg;
    for (; k + 4 <= end; k += 4) {
        int r0 = __ldg(g_src + k);
        int r1 = __ldg(g_src + k + 1);
        int r2 = __ldg(g_src + k + 2);
        int r3 = __ldg(g_src + k + 3);
        float4 v0 = h4_to_f4(__ldg(g_z1h + (size_t)r0 * 16 + j));
        float4 v1 = h4_to_f4(__ldg(g_z1h + (size_t)r1 * 16 + j));
        float4 v2 = h4_to_f4(__ldg(g_z1h + (size_t)r2 * 16 + j));
        float4 v3 = h4_to_f4(__ldg(g_z1h + (size_t)r3 * 16 + j));
        A0.x += v0.x; A0.y += v0.y; A0.z += v0.z; A0.w += v0.w;
        A1.x += v1.x; A1.y += v1.y; A1.z += v1.z; A1.w += v1.w;
        A2.x += v2.x; A2.y += v2.y; A2.z += v2.z; A2.w += v2.w;
        A3.x += v3.x; A3.y += v3.y; A3.z += v3.z; A3.w += v3.w;
    }
    if (k + 2 <= end) {
        int r0 = __ldg(g_src + k);
        int r1 = __ldg(g_src + k + 1);
        float4 v0 = h4_to_f4(__ldg(g_z1h + (size_t)r0 * 16 + j));
        float4 v1 = h4_to_f4(__ldg(g_z1h + (size_t)r1 * 16 + j));
        A0.x += v0.x; A0.y += v0.y; A0.z += v0.z; A0.w += v0.w;
        A1.x += v1.x; A1.y += v1.y; A1.z += v1.z; A1.w += v1.w;
        k += 2;
    }
    if (k < end) {
        int r0 = __ldg(g_src + k);
        float4 v0 = h4_to_f4(__ldg(g_z1h + (size_t)r0 * 16 + j));
        A2.x += v0.x; A2.y += v0.y; A2.z += v0.z; A2.w += v0.w;
    }

    float inv = __ldg((const float*)&g_si[node].x);
    float4 acc;
    acc.x = inv * ((A0.x + A1.x) + (A2.x + A3.x));
    acc.y = inv * ((A0.y + A1.y) + (A2.y + A3.y));
    acc.z = inv * ((A0.z + A1.z) + (A2.z + A3.z));
    acc.w = inv * ((A0.w + A1.w) + (A2.w + A3.w));
    g_z2h[(size_t)node * 16 + j] = f4_to_h4(acc);
}

// ---- final layer + combine:
// out = alpha * ( h0 + s*( z1 + z2 + inv * sum_r z2[r] ) ) ----
__global__ void k_gather_final() {
    int t = blockIdx.x * blockDim.x + threadIdx.x;
    int node = t >> 4;
    int j = t & 15;
    if (node >= NN) return;

    int beg = __ldg(g_off + node) + __ldg(g_bpre + (node >> 10));
    int end = beg + __ldg(g_deg + node);
    float4 A0 = make_float4(0.f, 0.f, 0.f, 0.f), A1 = A0, A2 = A0, A3 = A0;

    int k = beg;
    for (; k + 4 <= end; k += 4) {
        int r0 = __ldg(g_src + k);
        int r1 = __ldg(g_src + k + 1);
        int r2 = __ldg(g_src + k + 2);
        int r3 = __ldg(g_src + k + 3);
        float4 v0 = h4_to_f4(__ldg(g_z2h + (size_t)r0 * 16 + j));
        float4 v1 = h4_to_f4(__ldg(g_z2h + (size_t)r1 * 16 + j));
        float4 v2 = h4_to_f4(__ldg(g_z2h + (size_t)r2 * 16 + j));
        float4 v3 = h4_to_f4(__ldg(g_z2h + (size_t)r3 * 16 + j));
        A0.x += v0.x; A0.y += v0.y; A0.z += v0.z; A0.w += v0.w;
        A1.x += v1.x; A1.y += v1.y; A1.z += v1.z; A1.w += v1.w;
        A2.x += v2.x; A2.y += v2.y; A2.z += v2.z; A2.w += v2.w;
        A3.x += v3.x; A3.y += v3.y; A3.z += v3.z; A3.w += v3.w;
    }
    if (k + 2 <= end) {
        int r0 = __ldg(g_src + k);
        int r1 = __ldg(g_src + k + 1);
        float4 v0 = h4_to_f4(__ldg(g_z2h + (size_t)r0 * 16 + j));
        float4 v1 = h4_to_f4(__ldg(g_z2h + (size_t)r1 * 16 + j));
        A0.x += v0.x; A0.y += v0.y; A0.z += v0.z; A0.w += v0.w;
        A1.x += v1.x; A1.y += v1.y; A1.z += v1.z; A1.w += v1.w;
        k += 2;
    }
    if (k < end) {
        int r0 = __ldg(g_src + k);
        float4 v0 = h4_to_f4(__ldg(g_z2h + (size_t)r0 * 16 + j));
        A2.x += v0.x; A2.y += v0.y; A2.z += v0.z; A2.w += v0.w;
    }

    float2 si = __ldg(g_si + node);
    float inv = si.x, s = si.y;
    size_t idx = (size_t)node * 16 + j;
    float4 a = h4_to_f4(g_h0[idx]);
    float4 b = h4_to_f4(g_z1h[idx]);
    float4 c = h4_to_f4(g_z2h[idx]);
    float4 o;
    o.x = ALPHA * (a.x + s * (b.x + c.x + inv * ((A0.x + A1.x) + (A2.x + A3.x))));
    o.y = ALPHA * (a.y + s * (b.y + c.y + inv * ((A0.y + A1.y) + (A2.y + A3.y))));
    o.z = ALPHA * (a.z + s * (b.z + c.z + inv * ((A0.z + A1.z) + (A2.z + A3.z))));
    o.w = ALPHA * (a.w + s * (b.w + c.w + inv * ((A0.w + A1.w) + (A2.w + A3.w))));
    g_outh[idx] = f4_to_h4(o);
}

// ---- scoring: 8 lanes per pair, 16B fp16 loads, fp32 acc.
// Also re-zeroes g_deg/g_cur for the next invocation. ----
__global__ void k_score(const int* __restrict__ batch, float* __restrict__ out, int P) {
    int t = blockIdx.x * blockDim.x + threadIdx.x;
    if (t < NN) { g_deg[t] = 0; g_cur[t] = 0; }
    int p = t >> 3;
    int lane = t & 7;
    if (p >= P) return;
    int u = __ldg(batch + 3 * p);
    int v = __ldg(batch + 3 * p + 1);
    uint4 ua = __ldg((const uint4*)g_outh + (size_t)u * 8 + lane);
    uint4 ub = __ldg((const uint4*)g_outh + (size_t)v * 8 + lane);
    float4 a0 = h4_to_f4(make_uint2(ua.x, ua.y));
    float4 a1 = h4_to_f4(make_uint2(ua.z, ua.w));
    float4 b0 = h4_to_f4(make_uint2(ub.x, ub.y));
    float4 b1 = h4_to_f4(make_uint2(ub.z, ub.w));
    float s = a0.x * b0.x + a0.y * b0.y + a0.z * b0.z + a0.w * b0.w
            + a1.x * b1.x + a1.y * b1.y + a1.z * b1.z + a1.w * b1.w;
    #pragma unroll
    for (int o = 4; o; o >>= 1) s += __shfl_xor_sync(0xFFFFFFFFu, s, o);
    if (lane == 0) out[p] = s;
}

extern "C" void kernel_launch(void* const* d_in, const int* in_sizes, int n_in,
                              void* d_out, int out_size) {
    const float* emb   = (const float*)d_in[0];
    const int*   ei    = (const int*)d_in[1];
    const int*   batch = (const int*)d_in[2];
    float*       out   = (float*)d_out;

    int E = in_sizes[1] / 2;
    const int* row = ei;
    const int* col = ei + E;
    int P = in_sizes[2] / 3;

    k_count_half<<<(NV / 4 + 255) / 256, 256>>>(col, emb, E);
    k_scan1<<<NB_SCAN, 1024>>>();
    k_scan2<<<1, 256>>>();
    k_fill<<<(E + 255) / 256, 256>>>(row, col, E);

    int gthreads = NN * 16;
    int gblocks = (gthreads + 255) / 256;
    k_gather0<<<gblocks, 256>>>();
    k_gather1<<<gblocks, 256>>>();
    k_gather_final<<<gblocks, 256>>>();

    long long sthreads = (long long)P * 8;
    k_score<<<(int)((sthreads + 255) / 256), 256>>>(batch, out, P);
}